// round 14
// baseline (speedup 1.0000x reference)
#include <cuda_runtime.h>
#include <cstdint>

// DirectionalCurvatureLoss — fused stencil + curvature + |diff| mean, GB300.
// (pred,target) packed per-pixel into f32x2; R12 body (4 CTAs/SM @ 64 regs);
// ROWS=4 fine-grained tiles to kill wave-quantization tail; fused finalize.

#define Wd 1024
#define Hd 1024
#define ROWS 4
#define QW 4
#define TPB 256
#define EPSV 1e-8f

typedef unsigned long long u64;

__device__ float g_partials[8192];
__device__ unsigned int g_count;

__device__ __forceinline__ float f_rcp(float x) {
    float y; asm("rcp.approx.f32 %0, %1;" : "=f"(y) : "f"(x)); return y;
}
__device__ __forceinline__ float f_sqrt(float x) {
    float y; asm("sqrt.approx.f32 %0, %1;" : "=f"(y) : "f"(x)); return y;
}
__device__ __forceinline__ float f_rsqrt(float x) {
    float y; asm("rsqrt.approx.f32 %0, %1;" : "=f"(y) : "f"(x)); return y;
}

__device__ __forceinline__ u64 pk(float lo, float hi) {
    u64 r; asm("mov.b64 %0, {%1, %2};" : "=l"(r) : "f"(lo), "f"(hi)); return r;
}
__device__ __forceinline__ void unpk(u64 x, float& lo, float& hi) {
    asm("mov.b64 {%0, %1}, %2;" : "=f"(lo), "=f"(hi) : "l"(x));
}
__device__ __forceinline__ u64 fma2(u64 a, u64 b, u64 c) {
    u64 r; asm("fma.rn.f32x2 %0, %1, %2, %3;" : "=l"(r) : "l"(a), "l"(b), "l"(c)); return r;
}
__device__ __forceinline__ u64 add2(u64 a, u64 b) {
    u64 r; asm("add.rn.f32x2 %0, %1, %2;" : "=l"(r) : "l"(a), "l"(b)); return r;
}
__device__ __forceinline__ u64 mul2(u64 a, u64 b) {
    u64 r; asm("mul.rn.f32x2 %0, %1, %2;" : "=l"(r) : "l"(a), "l"(b)); return r;
}
#define PK2(c) pk((c), (c))

// Fetch row y and pack straight into 6 f32x2 (pred,target) pairs.
__device__ __forceinline__ void fetch_pack(const float* __restrict__ P,
                                           const float* __restrict__ T,
                                           int y, int x0, bool hasL, bool hasR,
                                           u64 out[6]) {
    if ((unsigned)y < (unsigned)Hd) {
        const float* rp = P + (y << 10) + x0;
        const float* rt = T + (y << 10) + x0;
        float4 vp = *reinterpret_cast<const float4*>(rp);
        float4 vt = *reinterpret_cast<const float4*>(rt);
        float h0p = hasL ? rp[-1] : 0.f;
        float h5p = hasR ? rp[4]  : 0.f;
        float h0t = hasL ? rt[-1] : 0.f;
        float h5t = hasR ? rt[4]  : 0.f;
        out[0] = pk(h0p,  h0t);
        out[1] = pk(vp.x, vt.x);
        out[2] = pk(vp.y, vt.y);
        out[3] = pk(vp.z, vt.z);
        out[4] = pk(vp.w, vt.w);
        out[5] = pk(h5p,  h5t);
    } else {
        #pragma unroll
        for (int i = 0; i < 6; i++) out[i] = 0ull;
    }
}

__global__ void __launch_bounds__(TPB, 4)
curv_loss_kernel(const float* __restrict__ pred, const float* __restrict__ target,
                 int nblocks, double invN, float* __restrict__ out) {
    const int x0 = threadIdx.x * QW;
    const int y0 = blockIdx.x * ROWS;
    const bool hasL = (x0 > 0);
    const bool hasR = (x0 + 4 < Wd);
    const size_t img_off = (size_t)blockIdx.y * (size_t)(Hd * Wd);
    const float* P = pred + img_off;
    const float* T = target + img_off;

    const u64 NEG1 = PK2(-1.f);
    const u64 TWO  = PK2(2.f);
    const u64 M3   = PK2(-3.f);
    const u64 ONE  = PK2(1.f);
    const u64 EPS2 = PK2(EPSV);
    const u64 C80  = PK2(1.f / 80.f);
    const u64 C3   = PK2(1.f / 3.f);   // r,t carry x100 (1/100 deferred to weights)
    const u64 CH   = PK2(0.5f);        // s term carries x100 as well
    #define SUB2(a, b) fma2((b), NEG1, (a))

    u64 ra[6], rb[6], rc[6];
    fetch_pack(P, T, y0 - 1, x0, hasL, hasR, ra);
    fetch_pack(P, T, y0,     x0, hasL, hasR, rb);

    float sp = 0.f, sl = 0.f, sm = 0.f;

    #pragma unroll
    for (int rr = 0; rr < ROWS; rr++) {
        fetch_pack(P, T, y0 + rr + 1, x0, hasL, hasR, rc);

        // minimal column precomputes: cs = colsum, dd = bottom-top
        u64 cs[6], dd[6];
        #pragma unroll
        for (int i = 0; i < 6; i++) {
            cs[i] = add2(add2(ra[i], rc[i]), rb[i]);
            dd[i] = SUB2(rc[i], ra[i]);
        }

        #pragma unroll
        for (int j = 0; j < 4; j++) {
            u64 S1 = add2(add2(cs[j], cs[j + 1]), cs[j + 2]);
            u64 S2 = add2(add2(rb[j], rb[j + 1]), rb[j + 2]);
            // w = cs + rb  =>  p stencil from cs & rb directly
            u64 p  = mul2(add2(SUB2(cs[j + 2], cs[j]), SUB2(rb[j + 2], rb[j])), C80);
            u64 q  = mul2(add2(fma2(dd[j + 1], TWO, dd[j]), dd[j + 2]), C80);
            u64 r  = mul2(fma2(cs[j + 1], M3, S1), C3);   // S1 - 3*cs[j+1]
            u64 tt = mul2(fma2(S2, M3, S1), C3);          // S1 - 3*S2
            u64 sn = mul2(SUB2(dd[j + 2], dd[j]), CH);    // = -(100*2*s_true)

            u64 p2 = mul2(p, p), q2 = mul2(q, q), pq = mul2(p, q);
            u64 d  = add2(p2, q2);
            u64 onepd = add2(d, ONE);

            float dl, dh, ol, oh;
            unpk(d, dl, dh); unpk(onepd, ol, oh);
            u64 rs1 = pk(f_rsqrt(ol), f_rsqrt(oh));
            u64 sqd = pk(f_sqrt(dl),  f_sqrt(dh));

            u64 sq1 = mul2(onepd, rs1);            // sqrt(1+d)
            u64 A = fma2(d, sq1, EPS2);            // d*sqrt(1+d)+eps
            u64 B = fma2(d, sqd, EPS2);            // d^1.5+eps
            u64 AB = mul2(A, B);
            float abl, abh; unpk(AB, abl, abh);
            float ipl = f_rcp(abl), iph = f_rcp(abh);
            if (dl < EPSV) ipl = 0.f;              // flat mask folded into 1/(A*B)
            if (dh < EPSV) iph = 0.f;
            u64 ip = pk(ipl, iph);
            u64 invA = mul2(ip, B);
            u64 invB = mul2(ip, A);
            u64 rs2  = mul2(rs1, rs1);
            u64 invC = mul2(rs2, rs1);             // (1+d)^-1.5  (x0.5 deferred)

            u64 s2n  = mul2(sn, pq);               // -2s*pq (x100)
            u64 core = fma2(tt, p2, fma2(r, q2, s2n));  // planform numerator
            u64 rt   = add2(r, tt);
            u64 n3   = add2(rt, core);                  // mean numerator
            u64 n1   = SUB2(mul2(rt, d), core);         // profile numerator

            u64 prof = mul2(n1, invA);
            u64 plan = mul2(core, invB);
            u64 mn   = mul2(n3, invC);

            float a0, a1;
            unpk(prof, a0, a1); sp += fabsf(a0 - a1);
            unpk(plan, a0, a1); sl += fabsf(a0 - a1);
            unpk(mn,   a0, a1); sm += fabsf(a0 - a1);
        }

        #pragma unroll
        for (int i = 0; i < 6; i++) { ra[i] = rb[i]; rb[i] = rc[i]; }
    }

    // ── deterministic block reduction ──────────────────────────────────
    #pragma unroll
    for (int off = 16; off > 0; off >>= 1) {
        sp += __shfl_xor_sync(0xFFFFFFFFu, sp, off);
        sl += __shfl_xor_sync(0xFFFFFFFFu, sl, off);
        sm += __shfl_xor_sync(0xFFFFFFFFu, sm, off);
    }
    __shared__ float sh[TPB / 32][3];
    __shared__ bool islast;
    int wid = threadIdx.x >> 5, lid = threadIdx.x & 31;
    if (lid == 0) { sh[wid][0] = sp; sh[wid][1] = sl; sh[wid][2] = sm; }
    __syncthreads();
    if (threadIdx.x == 0) {
        float a = 0.f, b = 0.f, c = 0.f;
        #pragma unroll
        for (int i = 0; i < TPB / 32; i++) { a += sh[i][0]; b += sh[i][1]; c += sh[i][2]; }
        int bid = blockIdx.y * gridDim.x + blockIdx.x;
        // weights (0.5, 0.3, 0.2*0.5); global 1/100 folded into invN
        g_partials[bid] = 0.5f * a + 0.3f * b + 0.1f * c;
        __threadfence();
        unsigned prev = atomicAdd(&g_count, 1u);
        islast = (prev == (unsigned)(nblocks - 1));
    }
    __syncthreads();

    if (islast) {
        __threadfence();
        __shared__ double shd[TPB];
        double acc = 0.0;
        for (int i = threadIdx.x; i < nblocks; i += TPB)
            acc += (double)g_partials[i];
        shd[threadIdx.x] = acc;
        __syncthreads();
        for (int off = TPB / 2; off > 0; off >>= 1) {
            if (threadIdx.x < off) shd[threadIdx.x] += shd[threadIdx.x + off];
            __syncthreads();
        }
        if (threadIdx.x == 0) {
            out[0] = (float)(shd[0] * invN);
            g_count = 0;   // reset for graph replay
        }
    }
}

extern "C" void kernel_launch(void* const* d_in, const int* in_sizes, int n_in,
                              void* d_out, int out_size) {
    const float* pred   = (const float*)d_in[0];
    const float* target = (const float*)d_in[1];
    float* out = (float*)d_out;

    int B = in_sizes[0] / (Hd * Wd);
    if (B < 1) B = 1;

    dim3 grid(Hd / ROWS, B);               // 256 x B = 4096 blocks
    int nblocks = (Hd / ROWS) * B;
    double invN = 0.01 / ((double)B * Hd * Wd);
    curv_loss_kernel<<<grid, TPB>>>(pred, target, nblocks, invN, out);
}

// round 15
// speedup vs baseline: 1.1312x; 1.1312x over previous
#include <cuda_runtime.h>
#include <cstdint>

// DirectionalCurvatureLoss — fused stencil + curvature + |diff| mean, GB300.
// (pred,target) packed per-pixel into f32x2; 4 CTAs/SM @ 64 regs; ROWS=8;
// L2 prefetch of row+2; parity-split accumulators; fused finalize.

#define Wd 1024
#define Hd 1024
#define ROWS 8
#define QW 4
#define TPB 256
#define EPSV 1e-8f

typedef unsigned long long u64;

__device__ float g_partials[8192];
__device__ unsigned int g_count;

__device__ __forceinline__ float f_rcp(float x) {
    float y; asm("rcp.approx.f32 %0, %1;" : "=f"(y) : "f"(x)); return y;
}
__device__ __forceinline__ float f_sqrt(float x) {
    float y; asm("sqrt.approx.f32 %0, %1;" : "=f"(y) : "f"(x)); return y;
}
__device__ __forceinline__ float f_rsqrt(float x) {
    float y; asm("rsqrt.approx.f32 %0, %1;" : "=f"(y) : "f"(x)); return y;
}

__device__ __forceinline__ u64 pk(float lo, float hi) {
    u64 r; asm("mov.b64 %0, {%1, %2};" : "=l"(r) : "f"(lo), "f"(hi)); return r;
}
__device__ __forceinline__ void unpk(u64 x, float& lo, float& hi) {
    asm("mov.b64 {%0, %1}, %2;" : "=f"(lo), "=f"(hi) : "l"(x));
}
__device__ __forceinline__ u64 fma2(u64 a, u64 b, u64 c) {
    u64 r; asm("fma.rn.f32x2 %0, %1, %2, %3;" : "=l"(r) : "l"(a), "l"(b), "l"(c)); return r;
}
__device__ __forceinline__ u64 add2(u64 a, u64 b) {
    u64 r; asm("add.rn.f32x2 %0, %1, %2;" : "=l"(r) : "l"(a), "l"(b)); return r;
}
__device__ __forceinline__ u64 mul2(u64 a, u64 b) {
    u64 r; asm("mul.rn.f32x2 %0, %1, %2;" : "=l"(r) : "l"(a), "l"(b)); return r;
}
#define PK2(c) pk((c), (c))

__device__ __forceinline__ void pf_l2(const float* p) {
    asm volatile("prefetch.global.L2 [%0];" :: "l"(p));
}

// Fetch row y and pack straight into 6 f32x2 (pred,target) pairs.
__device__ __forceinline__ void fetch_pack(const float* __restrict__ P,
                                           const float* __restrict__ T,
                                           int y, int x0, bool hasL, bool hasR,
                                           u64 out[6]) {
    if ((unsigned)y < (unsigned)Hd) {
        const float* rp = P + (y << 10) + x0;
        const float* rt = T + (y << 10) + x0;
        float4 vp = *reinterpret_cast<const float4*>(rp);
        float4 vt = *reinterpret_cast<const float4*>(rt);
        float h0p = hasL ? rp[-1] : 0.f;
        float h5p = hasR ? rp[4]  : 0.f;
        float h0t = hasL ? rt[-1] : 0.f;
        float h5t = hasR ? rt[4]  : 0.f;
        out[0] = pk(h0p,  h0t);
        out[1] = pk(vp.x, vt.x);
        out[2] = pk(vp.y, vt.y);
        out[3] = pk(vp.z, vt.z);
        out[4] = pk(vp.w, vt.w);
        out[5] = pk(h5p,  h5t);
    } else {
        #pragma unroll
        for (int i = 0; i < 6; i++) out[i] = 0ull;
    }
}

__global__ void __launch_bounds__(TPB, 4)
curv_loss_kernel(const float* __restrict__ pred, const float* __restrict__ target,
                 int nblocks, double invN, float* __restrict__ out) {
    const int x0 = threadIdx.x * QW;
    const int y0 = blockIdx.x * ROWS;
    const bool hasL = (x0 > 0);
    const bool hasR = (x0 + 4 < Wd);
    const size_t img_off = (size_t)blockIdx.y * (size_t)(Hd * Wd);
    const float* P = pred + img_off;
    const float* T = target + img_off;

    const u64 NEG1 = PK2(-1.f);
    const u64 TWO  = PK2(2.f);
    const u64 M3   = PK2(-3.f);
    const u64 ONE  = PK2(1.f);
    const u64 EPS2 = PK2(EPSV);
    const u64 C80  = PK2(1.f / 80.f);
    const u64 C3   = PK2(1.f / 3.f);   // r,t carry x100 (1/100 deferred to weights)
    const u64 CH   = PK2(0.5f);        // s term carries x100 as well
    #define SUB2(a, b) fma2((b), NEG1, (a))

    u64 ra[6], rb[6], rc[6];
    fetch_pack(P, T, y0 - 1, x0, hasL, hasR, ra);
    fetch_pack(P, T, y0,     x0, hasL, hasR, rb);

    float sp0 = 0.f, sl0 = 0.f, sm0 = 0.f;
    float sp1 = 0.f, sl1 = 0.f, sm1 = 0.f;

    #pragma unroll
    for (int rr = 0; rr < ROWS; rr++) {
        fetch_pack(P, T, y0 + rr + 1, x0, hasL, hasR, rc);

        // register-free prefetch of row (rr+2) into L2 (~1 body of lead)
        {
            int yp = y0 + rr + 2;
            if (yp > Hd - 1) yp = Hd - 1;
            pf_l2(P + (yp << 10) + x0);
            pf_l2(T + (yp << 10) + x0);
        }

        // minimal column precomputes: cs = colsum, dd = bottom-top
        u64 cs[6], dd[6];
        #pragma unroll
        for (int i = 0; i < 6; i++) {
            cs[i] = add2(add2(ra[i], rc[i]), rb[i]);
            dd[i] = SUB2(rc[i], ra[i]);
        }

        #pragma unroll
        for (int j = 0; j < 4; j++) {
            u64 S1 = add2(add2(cs[j], cs[j + 1]), cs[j + 2]);
            u64 S2 = add2(add2(rb[j], rb[j + 1]), rb[j + 2]);
            // w = cs + rb  =>  p stencil from cs & rb directly
            u64 p  = mul2(add2(SUB2(cs[j + 2], cs[j]), SUB2(rb[j + 2], rb[j])), C80);
            u64 q  = mul2(add2(fma2(dd[j + 1], TWO, dd[j]), dd[j + 2]), C80);
            u64 r  = mul2(fma2(cs[j + 1], M3, S1), C3);   // S1 - 3*cs[j+1]
            u64 tt = mul2(fma2(S2, M3, S1), C3);          // S1 - 3*S2
            u64 sn = mul2(SUB2(dd[j + 2], dd[j]), CH);    // = -(100*2*s_true)

            u64 p2 = mul2(p, p), q2 = mul2(q, q), pq = mul2(p, q);
            u64 d  = add2(p2, q2);
            u64 onepd = add2(d, ONE);

            float dl, dh, ol, oh;
            unpk(d, dl, dh); unpk(onepd, ol, oh);
            u64 rs1 = pk(f_rsqrt(ol), f_rsqrt(oh));
            u64 sqd = pk(f_sqrt(dl),  f_sqrt(dh));

            u64 sq1 = mul2(onepd, rs1);            // sqrt(1+d)
            u64 A = fma2(d, sq1, EPS2);            // d*sqrt(1+d)+eps
            u64 B = fma2(d, sqd, EPS2);            // d^1.5+eps
            u64 AB = mul2(A, B);
            float abl, abh; unpk(AB, abl, abh);
            float ipl = f_rcp(abl), iph = f_rcp(abh);
            if (dl < EPSV) ipl = 0.f;              // flat mask folded into 1/(A*B)
            if (dh < EPSV) iph = 0.f;
            u64 ip = pk(ipl, iph);
            u64 invA = mul2(ip, B);
            u64 invB = mul2(ip, A);
            u64 rs2  = mul2(rs1, rs1);
            u64 invC = mul2(rs2, rs1);             // (1+d)^-1.5  (x0.5 deferred)

            u64 s2n  = mul2(sn, pq);               // -2s*pq (x100)
            u64 core = fma2(tt, p2, fma2(r, q2, s2n));  // planform numerator
            u64 rt   = add2(r, tt);
            u64 n3   = add2(rt, core);                  // mean numerator
            u64 n1   = SUB2(mul2(rt, d), core);         // profile numerator

            u64 prof = mul2(n1, invA);
            u64 plan = mul2(core, invB);
            u64 mn   = mul2(n3, invC);

            float a0, a1;
            if (j & 1) {
                unpk(prof, a0, a1); sp1 += fabsf(a0 - a1);
                unpk(plan, a0, a1); sl1 += fabsf(a0 - a1);
                unpk(mn,   a0, a1); sm1 += fabsf(a0 - a1);
            } else {
                unpk(prof, a0, a1); sp0 += fabsf(a0 - a1);
                unpk(plan, a0, a1); sl0 += fabsf(a0 - a1);
                unpk(mn,   a0, a1); sm0 += fabsf(a0 - a1);
            }
        }

        #pragma unroll
        for (int i = 0; i < 6; i++) { ra[i] = rb[i]; rb[i] = rc[i]; }
    }

    float sp = sp0 + sp1, sl = sl0 + sl1, sm = sm0 + sm1;

    // ── deterministic block reduction ──────────────────────────────────
    #pragma unroll
    for (int off = 16; off > 0; off >>= 1) {
        sp += __shfl_xor_sync(0xFFFFFFFFu, sp, off);
        sl += __shfl_xor_sync(0xFFFFFFFFu, sl, off);
        sm += __shfl_xor_sync(0xFFFFFFFFu, sm, off);
    }
    __shared__ float sh[TPB / 32][3];
    __shared__ bool islast;
    int wid = threadIdx.x >> 5, lid = threadIdx.x & 31;
    if (lid == 0) { sh[wid][0] = sp; sh[wid][1] = sl; sh[wid][2] = sm; }
    __syncthreads();
    if (threadIdx.x == 0) {
        float a = 0.f, b = 0.f, c = 0.f;
        #pragma unroll
        for (int i = 0; i < TPB / 32; i++) { a += sh[i][0]; b += sh[i][1]; c += sh[i][2]; }
        int bid = blockIdx.y * gridDim.x + blockIdx.x;
        // weights (0.5, 0.3, 0.2*0.5); global 1/100 folded into invN
        g_partials[bid] = 0.5f * a + 0.3f * b + 0.1f * c;
        __threadfence();
        unsigned prev = atomicAdd(&g_count, 1u);
        islast = (prev == (unsigned)(nblocks - 1));
    }
    __syncthreads();

    if (islast) {
        __threadfence();
        __shared__ double shd[TPB];
        double acc = 0.0;
        for (int i = threadIdx.x; i < nblocks; i += TPB)
            acc += (double)g_partials[i];
        shd[threadIdx.x] = acc;
        __syncthreads();
        for (int off = TPB / 2; off > 0; off >>= 1) {
            if (threadIdx.x < off) shd[threadIdx.x] += shd[threadIdx.x + off];
            __syncthreads();
        }
        if (threadIdx.x == 0) {
            out[0] = (float)(shd[0] * invN);
            g_count = 0;   // reset for graph replay
        }
    }
}

extern "C" void kernel_launch(void* const* d_in, const int* in_sizes, int n_in,
                              void* d_out, int out_size) {
    const float* pred   = (const float*)d_in[0];
    const float* target = (const float*)d_in[1];
    float* out = (float*)d_out;

    int B = in_sizes[0] / (Hd * Wd);
    if (B < 1) B = 1;

    dim3 grid(Hd / ROWS, B);               // 128 x B blocks
    int nblocks = (Hd / ROWS) * B;
    double invN = 0.01 / ((double)B * Hd * Wd);
    curv_loss_kernel<<<grid, TPB>>>(pred, target, nblocks, invN, out);
}